// round 1
// baseline (speedup 1.0000x reference)
#include <cuda_runtime.h>
#include <math.h>

#define WW    5
#define LL    20
#define ROWI  105      // W*(1+L)
#define CEc   32
#define OCc   30
#define Kc    3
#define WEc   50
#define HIDc  100
#define TAGSc 36
#define QN    256
#define FCIN  400      // (WE+OC)*W
#define WSTR  80       // WE+OC

#define NW 16
#define NT (NW*32)

// ---- precomputed tables (device globals: allocation-free scratch) ----
__device__ float g_P[Kc*100*OCc];        // [k][c][oc]
__device__ float g_Q[WW*QN*HIDc];        // [w][id][j]

// P[k][c][oc] = sum_ce conv_w[oc,ce,k] * char_emb[c,ce]
__global__ void prep_P(const float* __restrict__ conv_w,
                       const float* __restrict__ char_emb) {
    int i = blockIdx.x*blockDim.x + threadIdx.x;
    if (i >= Kc*100*OCc) return;
    int oc = i % OCc;
    int c  = (i / OCc) % 100;
    int k  = i / (OCc*100);
    float s = 0.f;
    #pragma unroll
    for (int ce = 0; ce < CEc; ce++)
        s += conv_w[(oc*CEc + ce)*Kc + k] * char_emb[c*CEc + ce];
    g_P[i] = s;   // i == (k*100 + c)*OCc + oc
}

// Q[w][id][j] = sum_d emb[id,d] * fc1_w[j, w*80 + d]
__global__ void prep_Q(const float* __restrict__ emb,
                       const float* __restrict__ fc1_w) {
    int i = blockIdx.x*blockDim.x + threadIdx.x;
    if (i >= WW*QN*HIDc) return;
    int j = i % HIDc;
    int c = (i / HIDc) % QN;
    int w = i / (HIDc*QN);
    const float* e  = emb + c*WEc;
    const float* fr = fc1_w + j*FCIN + w*WSTR;
    float s = 0.f;
    #pragma unroll
    for (int d = 0; d < WEc; d++) s += e[d]*fr[d];
    g_Q[i] = s;
}

// smem floats: P 9000 | Wp 15000 | OwT 3600 | fc1b 100 | outb 40 | convb 32 | warp scratch NW*384
#define SM_FIXED (9000 + 15000 + 3600 + 100 + 40 + 32)
#define SM_WARP  384
#define SM_FLOATS (SM_FIXED + NW*SM_WARP)
#define SM_BYTES (SM_FLOATS * 4)

__global__ __launch_bounds__(NT) void pos_main(
    const int*   __restrict__ input,
    const float* __restrict__ emb,
    const float* __restrict__ conv_b,
    const float* __restrict__ fc1_w,
    const float* __restrict__ fc1_b,
    const float* __restrict__ out_w,
    const float* __restrict__ out_b,
    float*       __restrict__ out,
    int nb)
{
    extern __shared__ float sm[];
    float* sP   = sm;              // 9000 : [k][c][oc]
    float* sWp  = sP   + 9000;     // 15000: [w*30+oc][j]  (fc1 pooled-part weights)
    float* sOwT = sWp  + 15000;    // 3600 : [j][t]        (out_w transposed)
    float* sFb  = sOwT + 3600;     // 100
    float* sOb  = sFb  + 100;      // 40
    float* sCb  = sOb  + 40;       // 32
    float* sWsc = sCb  + 32;       // NW*384 per-warp scratch

    const int tid = threadIdx.x;

    for (int i = tid; i < Kc*100*OCc; i += NT) sP[i] = g_P[i];
    for (int i = tid; i < WW*OCc*HIDc; i += NT) {
        int row = i / HIDc, j = i % HIDc;
        int w = row / OCc, oc = row % OCc;
        sWp[i] = fc1_w[j*FCIN + w*WSTR + WEc + oc];
    }
    for (int i = tid; i < HIDc*TAGSc; i += NT) {
        int j = i / TAGSc, t = i % TAGSc;
        sOwT[i] = out_w[t*HIDc + j];
    }
    if (tid < HIDc)  sFb[tid] = fc1_b[tid];
    if (tid < TAGSc) sOb[tid] = out_b[tid];
    if (tid < OCc)   sCb[tid] = conv_b[tid];
    __syncthreads();

    const int warp = tid >> 5, lane = tid & 31;
    int*   sIds  = (int*)(sWsc + warp*SM_WARP);       // 112 ints (ids of item)
    float* sPool = sWsc + warp*SM_WARP + 112;         // 160 (pooled, 5*30)
    float* sH    = sWsc + warp*SM_WARP + 272;         // 112 (hidden)

    const int  j0   = lane * 4;          // lane<25 handles j0..j0+3
    const bool jact = (lane < 25);

    for (int item = blockIdx.x*NW + warp; item < nb; item += gridDim.x*NW) {
        const int* inrow = input + item*ROWI;
        for (int p = lane; p < ROWI; p += 32) sIds[p] = inrow[p];
        __syncwarp();

        // ---- fc1 accumulators: word-embedding part via Q table ----
        float a0 = 0.f, a1 = 0.f, a2 = 0.f, a3 = 0.f;
        if (jact) {
            #pragma unroll
            for (int w = 0; w < WW; w++) {
                int id = sIds[w*(1+LL)];
                if (id < QN) {
                    const float4 q = *(const float4*)&g_Q[(w*QN + id)*HIDc + j0];
                    a0 += q.x; a1 += q.y; a2 += q.z; a3 += q.w;
                } else {
                    // never taken for this dataset (ids < 100); exact fallback
                    const float* e = emb + (long)id*WEc;
                    #pragma unroll 1
                    for (int d = 0; d < WEc; d++) {
                        float ev = e[d];
                        a0 += ev * fc1_w[(j0+0)*FCIN + w*WSTR + d];
                        a1 += ev * fc1_w[(j0+1)*FCIN + w*WSTR + d];
                        a2 += ev * fc1_w[(j0+2)*FCIN + w*WSTR + d];
                        a3 += ev * fc1_w[(j0+3)*FCIN + w*WSTR + d];
                    }
                }
            }
        }

        // ---- conv + maxpool via P tables; lane == oc ----
        if (lane < OCc) {
            #pragma unroll 1
            for (int w = 0; w < WW; w++) {
                int cc[LL];
                #pragma unroll
                for (int p = 0; p < LL; p++) cc[p] = sIds[w*(1+LL) + 1 + p];
                float m = -3.4e38f;
                #pragma unroll
                for (int t = 0; t < LL-Kc+1; t++) {
                    float v = sP[cc[t  ]*OCc + lane]
                            + sP[3000 + cc[t+1]*OCc + lane]
                            + sP[6000 + cc[t+2]*OCc + lane];
                    m = fmaxf(m, v);
                }
                sPool[w*OCc + lane] = m + sCb[lane];
            }
        }
        __syncwarp();

        // ---- fc1 pooled part + tanh ----
        if (jact) {
            #pragma unroll 5
            for (int r = 0; r < WW*OCc; r++) {
                float pv = sPool[r];
                const float4 wv = *(const float4*)&sWp[r*HIDc + j0];
                a0 += pv*wv.x; a1 += pv*wv.y; a2 += pv*wv.z; a3 += pv*wv.w;
            }
            sH[j0+0] = tanhf(a0 + sFb[j0+0]);
            sH[j0+1] = tanhf(a1 + sFb[j0+1]);
            sH[j0+2] = tanhf(a2 + sFb[j0+2]);
            sH[j0+3] = tanhf(a3 + sFb[j0+3]);
        }
        __syncwarp();

        // ---- output layer: lane handles t=lane, lanes 0..3 also t=32+lane ----
        float o1 = 0.f, o2 = 0.f;
        #pragma unroll 4
        for (int j = 0; j < HIDc; j++) {
            float hj = sH[j];
            o1 += hj * sOwT[j*TAGSc + lane];
            if (lane < 4) o2 += hj * sOwT[j*TAGSc + 32 + lane];
        }
        float* orow = out + (long)item*TAGSc;
        orow[lane] = o1 + sOb[lane];
        if (lane < 4) orow[32 + lane] = o2 + sOb[32 + lane];
        __syncwarp();
    }
}

extern "C" void kernel_launch(void* const* d_in, const int* in_sizes, int n_in,
                              void* d_out, int out_size) {
    const int*   input = (const int*)  d_in[0];
    const float* emb   = (const float*)d_in[1];
    const float* cemb  = (const float*)d_in[2];
    const float* convw = (const float*)d_in[3];
    const float* convb = (const float*)d_in[4];
    const float* fc1w  = (const float*)d_in[5];
    const float* fc1b  = (const float*)d_in[6];
    const float* outw  = (const float*)d_in[7];
    const float* outb  = (const float*)d_in[8];
    float* out = (float*)d_out;

    int nb = in_sizes[0] / ROWI;

    cudaFuncSetAttribute(pos_main, cudaFuncAttributeMaxDynamicSharedMemorySize, SM_BYTES);

    prep_P<<<(Kc*100*OCc + 255)/256, 256>>>(convw, cemb);
    prep_Q<<<(WW*QN*HIDc + 255)/256, 256>>>(emb, fc1w);

    int blocks = (nb + NW - 1) / NW;
    pos_main<<<blocks, NT, SM_BYTES>>>(input, emb, convb, fc1w, fc1b, outw, outb, out, nb);
}

// round 2
// speedup vs baseline: 2.0311x; 2.0311x over previous
#include <cuda_runtime.h>
#include <cuda_fp16.h>
#include <math.h>

#define WW    5
#define LL    20
#define ROWI  105      // W*(1+L)
#define CEc   32
#define OCc   30
#define Kc    3
#define WEc   50
#define HIDc  100
#define TAGSc 36
#define QN    256
#define FCIN  400      // (WE+OC)*W
#define WSTR  80       // WE+OC

#define NW 16
#define NT (NW*32)
#define IT 4           // items per warp

// ---- precomputed tables (device globals: allocation-free scratch) ----
__device__ __half g_P4[100*OCc*4];     // [c][oc][k0,k1,k2,pad]  fp16
__device__ float  g_Q [WW*QN*HIDc];    // [w][id][j]
__device__ float  g_Wp[WW*OCc*HIDc];   // [r=w*30+oc][j]  (fc1 pooled-part, pre-transposed)

// P[c][oc][k] = sum_ce conv_w[oc,ce,k] * char_emb[c,ce]   (fp16 pack)
__global__ void prep_P(const float* __restrict__ conv_w,
                       const float* __restrict__ char_emb) {
    int i = blockIdx.x*blockDim.x + threadIdx.x;
    if (i >= 100*OCc) return;
    int oc = i % OCc, c = i / OCc;
    float s0 = 0.f, s1 = 0.f, s2 = 0.f;
    #pragma unroll
    for (int ce = 0; ce < CEc; ce++) {
        float e = char_emb[c*CEc + ce];
        const float* w = &conv_w[(oc*CEc + ce)*Kc];
        s0 += w[0]*e; s1 += w[1]*e; s2 += w[2]*e;
    }
    __half2* dst = (__half2*)&g_P4[i*4];
    dst[0] = __floats2half2_rn(s0, s1);
    dst[1] = __floats2half2_rn(s2, 0.f);
}

// Q[w][id][j] = sum_d emb[id,d] * fc1_w[j, w*80 + d]
__global__ void prep_Q(const float* __restrict__ emb,
                       const float* __restrict__ fc1_w) {
    int i = blockIdx.x*blockDim.x + threadIdx.x;
    if (i >= WW*QN*HIDc) return;
    int j = i % HIDc;
    int c = (i / HIDc) % QN;
    int w = i / (HIDc*QN);
    const float* e  = emb + c*WEc;
    const float* fr = fc1_w + j*FCIN + w*WSTR;
    float s = 0.f;
    #pragma unroll
    for (int d = 0; d < WEc; d++) s += e[d]*fr[d];
    g_Q[i] = s;
}

// Wp[r][j] = fc1_w[j, w*80 + 50 + oc],  r = w*30+oc  (transpose once in global)
__global__ void prep_W(const float* __restrict__ fc1_w) {
    int i = blockIdx.x*blockDim.x + threadIdx.x;
    if (i >= WW*OCc*HIDc) return;
    int j = i % HIDc, r = i / HIDc;
    int w = r / OCc, oc = r % OCc;
    g_Wp[i] = fc1_w[j*FCIN + w*WSTR + WEc + oc];
}

// ---- smem layout (float units) ----
// sP4 (half, 6000 fl) | sWp 15000 | sOw 36*104=3744 | fc1b 100 | outb 40 | convb 32 | pad
#define OFF_WP   6000
#define OFF_OW   21000
#define OFF_FB   24744
#define OFF_OB   24844
#define OFF_CB   24884
#define OFF_WS   24920          // warp scratch base (16B aligned: 24920*4=99680)
#define WS_STRIDE 1456          // per-warp floats (ids 432i | poolT 600 | H 416 | pad)
#define SM_FLOATS (OFF_WS + NW*WS_STRIDE)
#define SM_BYTES  (SM_FLOATS*4)

__global__ __launch_bounds__(NT) void pos_main(
    const int*   __restrict__ input,
    const float* __restrict__ emb,
    const float* __restrict__ conv_b,
    const float* __restrict__ fc1_w,
    const float* __restrict__ fc1_b,
    const float* __restrict__ out_w,
    const float* __restrict__ out_b,
    float*       __restrict__ out,
    int nb)
{
    extern __shared__ float sm[];
    __half* sP4 = (__half*)sm;
    float*  sWp = sm + OFF_WP;
    float*  sOw = sm + OFF_OW;     // [t][104]
    float*  sFb = sm + OFF_FB;
    float*  sOb = sm + OFF_OB;
    float*  sCb = sm + OFF_CB;

    const int tid = threadIdx.x;

    // -- fill shared weights (contiguous copies) --
    {
        const int4* src = (const int4*)g_P4;   // 24000B = 1500 int4
        int4* dst = (int4*)sP4;
        for (int i = tid; i < 1500; i += NT) dst[i] = src[i];
        const int4* ws = (const int4*)g_Wp;    // 60000B = 3750 int4
        int4* wd = (int4*)sWp;
        for (int i = tid; i < 3750; i += NT) wd[i] = ws[i];
        for (int i = tid; i < TAGSc*104; i += NT) {
            int t = i / 104, j = i % 104;
            sOw[i] = (j < HIDc) ? out_w[t*HIDc + j] : 0.f;
        }
        if (tid < HIDc)  sFb[tid] = fc1_b[tid];
        if (tid < TAGSc) sOb[tid] = out_b[tid];
        if (tid < OCc)   sCb[tid] = conv_b[tid];
    }
    __syncthreads();

    const int warp = tid >> 5, lane = tid & 31;
    float* ws    = sm + OFF_WS + warp*WS_STRIDE;
    int*   sIds  = (int*)ws;            // 420 used
    float* sPoolT= ws + 432;            // [r][IT] 600
    float* sH    = ws + 1032;           // [it][104] 416

    const int group = blockIdx.x*NW + warp;
    const int base  = group*IT;
    if (base >= nb) return;
    const int nit = (nb - base < IT) ? (nb - base) : IT;

    // -- load ids for up to 4 items --
    for (int i = lane; i < nit*ROWI; i += 32) sIds[i] = input[base*ROWI + i];
    __syncwarp();

    // -- fc1 accumulators; word-embedding part via Q table --
    float a[IT][4] = {};
    const int j0 = lane*4;
    const bool jact = (lane < 25);
    if (jact) {
        for (int it = 0; it < nit; it++) {
            #pragma unroll
            for (int w = 0; w < WW; w++) {
                int id = sIds[it*ROWI + w*(1+LL)];
                if (id < QN) {
                    const float4 q = *(const float4*)&g_Q[(w*QN + id)*HIDc + j0];
                    a[it][0] += q.x; a[it][1] += q.y; a[it][2] += q.z; a[it][3] += q.w;
                } else {   // exact fallback (never taken for this data)
                    const float* e = emb + (long)id*WEc;
                    #pragma unroll 1
                    for (int d = 0; d < WEc; d++) {
                        float ev = e[d];
                        a[it][0] += ev * fc1_w[(j0+0)*FCIN + w*WSTR + d];
                        a[it][1] += ev * fc1_w[(j0+1)*FCIN + w*WSTR + d];
                        a[it][2] += ev * fc1_w[(j0+2)*FCIN + w*WSTR + d];
                        a[it][3] += ev * fc1_w[(j0+3)*FCIN + w*WSTR + d];
                    }
                }
            }
        }
    }

    // -- conv + maxpool via fp16 P table; lane == oc; rolling 3-window --
    if (lane < OCc) {
        for (int it = 0; it < nit; it++) {
            #pragma unroll 1
            for (int w = 0; w < WW; w++) {
                const int* cc = &sIds[it*ROWI + w*(1+LL) + 1];
                float m = -3.4e38f;
                float p02 = 0.f, p01 = 0.f, p11 = 0.f;
                #pragma unroll
                for (int p = 0; p < LL; p++) {
                    int c = cc[p];
                    uint2 raw = *(const uint2*)&sP4[(c*OCc + lane)*4];
                    float2 f01 = __half22float2(*(__half2*)&raw.x);
                    float  f2  = __low2float(*(__half2*)&raw.y);
                    if (p >= 2) m = fmaxf(m, p02 + p11 + f2);
                    p02 = p01; p01 = f01.x; p11 = f01.y;
                }
                sPoolT[(w*OCc + lane)*IT + it] = m + sCb[lane];
            }
        }
    }
    __syncwarp();

    // -- fc1 pooled part (weights reused across IT items) + tanh --
    if (jact) {
        const float4* wp4 = (const float4*)sWp;
        const float4* pp4 = (const float4*)sPoolT;
        #pragma unroll 2
        for (int r = 0; r < WW*OCc; r++) {
            float4 wv = wp4[r*25 + lane];
            float4 pv = pp4[r];                       // [item0..3] broadcast
            a[0][0] += pv.x*wv.x; a[0][1] += pv.x*wv.y; a[0][2] += pv.x*wv.z; a[0][3] += pv.x*wv.w;
            a[1][0] += pv.y*wv.x; a[1][1] += pv.y*wv.y; a[1][2] += pv.y*wv.z; a[1][3] += pv.y*wv.w;
            a[2][0] += pv.z*wv.x; a[2][1] += pv.z*wv.y; a[2][2] += pv.z*wv.z; a[2][3] += pv.z*wv.w;
            a[3][0] += pv.w*wv.x; a[3][1] += pv.w*wv.y; a[3][2] += pv.w*wv.z; a[3][3] += pv.w*wv.w;
        }
        #pragma unroll
        for (int it = 0; it < IT; it++) {
            float4 hb;
            hb.x = tanhf(a[it][0] + sFb[j0+0]);
            hb.y = tanhf(a[it][1] + sFb[j0+1]);
            hb.z = tanhf(a[it][2] + sFb[j0+2]);
            hb.w = tanhf(a[it][3] + sFb[j0+3]);
            *(float4*)&sH[it*104 + j0] = hb;
        }
    }
    __syncwarp();

    // -- output layer: lane t=lane (all 32), lanes 0..3 also t=32+lane --
    float o1[IT] = {}, o2[IT] = {};
    const float4* owr  = (const float4*)(sOw + lane*104);
    const float4* owr2 = (const float4*)(sOw + (32+lane)*104);   // lane<4
    #pragma unroll 5
    for (int jq = 0; jq < HIDc/4; jq++) {
        float4 wv = owr[jq];
        float4 h0 = *(const float4*)&sH[0*104 + jq*4];
        float4 h1 = *(const float4*)&sH[1*104 + jq*4];
        float4 h2 = *(const float4*)&sH[2*104 + jq*4];
        float4 h3 = *(const float4*)&sH[3*104 + jq*4];
        o1[0] += wv.x*h0.x + wv.y*h0.y + wv.z*h0.z + wv.w*h0.w;
        o1[1] += wv.x*h1.x + wv.y*h1.y + wv.z*h1.z + wv.w*h1.w;
        o1[2] += wv.x*h2.x + wv.y*h2.y + wv.z*h2.z + wv.w*h2.w;
        o1[3] += wv.x*h3.x + wv.y*h3.y + wv.z*h3.z + wv.w*h3.w;
        if (lane < 4) {
            float4 w2 = owr2[jq];
            o2[0] += w2.x*h0.x + w2.y*h0.y + w2.z*h0.z + w2.w*h0.w;
            o2[1] += w2.x*h1.x + w2.y*h1.y + w2.z*h1.z + w2.w*h1.w;
            o2[2] += w2.x*h2.x + w2.y*h2.y + w2.z*h2.z + w2.w*h2.w;
            o2[3] += w2.x*h3.x + w2.y*h3.y + w2.z*h3.z + w2.w*h3.w;
        }
    }
    for (int it = 0; it < nit; it++) {
        out[(long)(base+it)*TAGSc + lane] = o1[it] + sOb[lane];
        if (lane < 4)
            out[(long)(base+it)*TAGSc + 32 + lane] = o2[it] + sOb[32+lane];
    }
}

extern "C" void kernel_launch(void* const* d_in, const int* in_sizes, int n_in,
                              void* d_out, int out_size) {
    const int*   input = (const int*)  d_in[0];
    const float* emb   = (const float*)d_in[1];
    const float* cemb  = (const float*)d_in[2];
    const float* convw = (const float*)d_in[3];
    const float* convb = (const float*)d_in[4];
    const float* fc1w  = (const float*)d_in[5];
    const float* fc1b  = (const float*)d_in[6];
    const float* outw  = (const float*)d_in[7];
    const float* outb  = (const float*)d_in[8];
    float* out = (float*)d_out;

    int nb = in_sizes[0] / ROWI;

    cudaFuncSetAttribute(pos_main, cudaFuncAttributeMaxDynamicSharedMemorySize, SM_BYTES);

    prep_P<<<(100*OCc + 255)/256, 256>>>(convw, cemb);
    prep_Q<<<(WW*QN*HIDc + 255)/256, 256>>>(emb, fc1w);
    prep_W<<<(WW*OCc*HIDc + 255)/256, 256>>>(fc1w);

    int blocks = (nb + NW*IT - 1) / (NW*IT);
    pos_main<<<blocks, NT, SM_BYTES>>>(input, emb, convb, fc1w, fc1b, outw, outb, out, nb);
}

// round 3
// speedup vs baseline: 2.5514x; 1.2562x over previous
#include <cuda_runtime.h>
#include <cuda_fp16.h>
#include <math.h>

#define WW    5
#define LL    20
#define ROWI  105      // W*(1+L)
#define CEc   32
#define OCc   30
#define Kc    3
#define WEc   50
#define HIDc  100
#define TAGSc 36
#define QN    256
#define FCIN  400      // (WE+OC)*W
#define WSTR  80       // WE+OC

#define NW 32
#define NT (NW*32)
#define IT 4           // items per warp

#define NQ (WW*QN*HIDc)        // 128000
#define NWP (WW*OCc*HIDc)      // 15000
#define NP (100*OCc)           // 3000

// ---- precomputed tables (device globals: allocation-free scratch) ----
__device__ __half g_P4[100*OCc*4];     // [c][oc][k0,k1,k2,pad]  fp16
__device__ float  g_Q [NQ];            // [w][id][j]
__device__ __half g_WpH[NWP];          // [r=w*30+oc][j]  fp16, pre-transposed

__device__ __forceinline__ float tanh_ap(float x) {
    float y; asm("tanh.approx.f32 %0, %1;" : "=f"(y) : "f"(x)); return y;
}

// one fused prep launch: Q | WpH | P4
__global__ void prep_all(const float* __restrict__ conv_w,
                         const float* __restrict__ char_emb,
                         const float* __restrict__ emb,
                         const float* __restrict__ fc1_w) {
    int i = blockIdx.x*blockDim.x + threadIdx.x;
    if (i < NQ) {
        int j = i % HIDc;
        int c = (i / HIDc) % QN;
        int w = i / (HIDc*QN);
        const float* e  = emb + c*WEc;
        const float* fr = fc1_w + j*FCIN + w*WSTR;
        float s = 0.f;
        #pragma unroll
        for (int d = 0; d < WEc; d++) s += e[d]*fr[d];
        g_Q[i] = s;
    } else if (i < NQ + NWP) {
        int k = i - NQ;
        int j = k % HIDc, r = k / HIDc;
        int w = r / OCc, oc = r % OCc;
        g_WpH[k] = __float2half_rn(fc1_w[j*FCIN + w*WSTR + WEc + oc]);
    } else if (i < NQ + NWP + NP) {
        int k = i - NQ - NWP;
        int oc = k % OCc, c = k / OCc;
        float s0 = 0.f, s1 = 0.f, s2 = 0.f;
        #pragma unroll
        for (int ce = 0; ce < CEc; ce++) {
            float e = char_emb[c*CEc + ce];
            const float* w = &conv_w[(oc*CEc + ce)*Kc];
            s0 += w[0]*e; s1 += w[1]*e; s2 += w[2]*e;
        }
        __half2* dst = (__half2*)&g_P4[k*4];
        dst[0] = __floats2half2_rn(s0, s1);
        dst[1] = __floats2half2_rn(s2, 0.f);
    }
}

// ---- smem layout (bytes) ----
#define OFFB_P4   0          // 24000  half [c][oc][4]
#define OFFB_WPH  24000      // 30000  half [r][100]
#define OFFB_OWH  54000      // 36*216 = 7776  half [t][stride 108]
#define OWH_STRIDE 108       // halves; 216B rows (2-way max bank pattern)
#define OFFB_FB   61776      // 400
#define OFFB_OB   62176      // 160
#define OFFB_CB   62336      // 128
#define OFFB_WS   62464      // warp scratch
#define WSB       4960       // per warp: ids u16 896 | poolT f32 2400 | sH f32 1664
#define SM_BYTES  (OFFB_WS + NW*WSB)   // 221184 = 216KB

__global__ __launch_bounds__(NT) void pos_main(
    const int*   __restrict__ input,
    const float* __restrict__ emb,
    const float* __restrict__ conv_b,
    const float* __restrict__ fc1_w,
    const float* __restrict__ fc1_b,
    const float* __restrict__ out_w,
    const float* __restrict__ out_b,
    float*       __restrict__ out,
    int nb)
{
    extern __shared__ char smb[];
    __half* sP4  = (__half*)(smb + OFFB_P4);
    __half* sWpH = (__half*)(smb + OFFB_WPH);
    __half* sOwH = (__half*)(smb + OFFB_OWH);
    float*  sFb  = (float*)(smb + OFFB_FB);
    float*  sOb  = (float*)(smb + OFFB_OB);
    float*  sCb  = (float*)(smb + OFFB_CB);

    const int tid = threadIdx.x;

    // -- fill shared weights --
    {
        const int4* ps = (const int4*)g_P4;            // 1500 int4
        int4* pd = (int4*)sP4;
        for (int i = tid; i < 1500; i += NT) pd[i] = ps[i];
        const int4* ws = (const int4*)g_WpH;           // 1875 int4
        int4* wd = (int4*)sWpH;
        for (int i = tid; i < 1875; i += NT) wd[i] = ws[i];
        for (int i = tid; i < TAGSc*OWH_STRIDE; i += NT) {
            int t = i / OWH_STRIDE, j = i % OWH_STRIDE;
            sOwH[i] = (j < HIDc) ? __float2half_rn(out_w[t*HIDc + j]) : __half(0.f);
        }
        if (tid < HIDc)  sFb[tid] = fc1_b[tid];
        if (tid < TAGSc) sOb[tid] = out_b[tid];
        if (tid < OCc)   sCb[tid] = conv_b[tid];
    }
    __syncthreads();

    const int warp = tid >> 5, lane = tid & 31;
    char* ws = smb + OFFB_WS + warp*WSB;
    unsigned short* sIds = (unsigned short*)ws;         // 420 used (u16)
    float* sPoolT = (float*)(ws + 896);                 // [r][IT] 600 f
    float* sH     = (float*)(ws + 3296);                // [it][104] 416 f

    const int j0 = lane*4;
    const bool jact = (lane < 25);
    const int ngroups = (nb + IT - 1) / IT;

    for (int group = blockIdx.x*NW + warp; group < ngroups; group += gridDim.x*NW) {
        const int base = group*IT;
        const int nit = (nb - base < IT) ? (nb - base) : IT;

        for (int i = lane; i < nit*ROWI; i += 32)
            sIds[i] = (unsigned short)input[base*ROWI + i];
        __syncwarp();

        // -- fc1 accumulators; word-embedding part via Q table --
        float a[IT][4] = {};
        if (jact) {
            for (int it = 0; it < nit; it++) {
                #pragma unroll
                for (int w = 0; w < WW; w++) {
                    int id = sIds[it*ROWI + w*(1+LL)];
                    if (id < QN) {
                        const float4 q = *(const float4*)&g_Q[(w*QN + id)*HIDc + j0];
                        a[it][0] += q.x; a[it][1] += q.y; a[it][2] += q.z; a[it][3] += q.w;
                    } else {   // exact fallback (never taken for this data)
                        const float* e = emb + (long)id*WEc;
                        #pragma unroll 1
                        for (int d = 0; d < WEc; d++) {
                            float ev = e[d];
                            a[it][0] += ev * fc1_w[(j0+0)*FCIN + w*WSTR + d];
                            a[it][1] += ev * fc1_w[(j0+1)*FCIN + w*WSTR + d];
                            a[it][2] += ev * fc1_w[(j0+2)*FCIN + w*WSTR + d];
                            a[it][3] += ev * fc1_w[(j0+3)*FCIN + w*WSTR + d];
                        }
                    }
                }
            }
        }

        // -- conv + maxpool via fp16 P; lane == oc; rolling 3-window --
        if (lane < OCc) {
            for (int it = 0; it < nit; it++) {
                #pragma unroll 1
                for (int w = 0; w < WW; w++) {
                    const unsigned short* cc = &sIds[it*ROWI + w*(1+LL) + 1];
                    float m = -3.4e38f;
                    float p02 = 0.f, p01 = 0.f, p11 = 0.f;
                    #pragma unroll
                    for (int p = 0; p < LL; p++) {
                        int c = cc[p];
                        uint2 raw = *(const uint2*)&sP4[(c*OCc + lane)*4];
                        float2 f01 = __half22float2(*(__half2*)&raw.x);
                        float  f2  = __low2float(*(__half2*)&raw.y);
                        if (p >= 2) m = fmaxf(m, p02 + p11 + f2);
                        p02 = p01; p01 = f01.x; p11 = f01.y;
                    }
                    sPoolT[(w*OCc + lane)*IT + it] = m + sCb[lane];
                }
            }
        }
        __syncwarp();

        // -- fc1 pooled part: fp16 weights reused across IT items, then tanh --
        if (jact) {
            const uint2* wp = (const uint2*)sWpH;       // row = 25 uint2
            const float4* pp4 = (const float4*)sPoolT;
            #pragma unroll 2
            for (int r = 0; r < WW*OCc; r++) {
                uint2 wraw = wp[r*25 + lane];
                float2 w01 = __half22float2(*(__half2*)&wraw.x);
                float2 w23 = __half22float2(*(__half2*)&wraw.y);
                float4 pv = pp4[r];                     // [item0..3] broadcast
                a[0][0] += pv.x*w01.x; a[0][1] += pv.x*w01.y; a[0][2] += pv.x*w23.x; a[0][3] += pv.x*w23.y;
                a[1][0] += pv.y*w01.x; a[1][1] += pv.y*w01.y; a[1][2] += pv.y*w23.x; a[1][3] += pv.y*w23.y;
                a[2][0] += pv.z*w01.x; a[2][1] += pv.z*w01.y; a[2][2] += pv.z*w23.x; a[2][3] += pv.z*w23.y;
                a[3][0] += pv.w*w01.x; a[3][1] += pv.w*w01.y; a[3][2] += pv.w*w23.x; a[3][3] += pv.w*w23.y;
            }
            #pragma unroll
            for (int it = 0; it < IT; it++) {
                float4 hb;
                hb.x = tanh_ap(a[it][0] + sFb[j0+0]);
                hb.y = tanh_ap(a[it][1] + sFb[j0+1]);
                hb.z = tanh_ap(a[it][2] + sFb[j0+2]);
                hb.w = tanh_ap(a[it][3] + sFb[j0+3]);
                *(float4*)&sH[it*104 + j0] = hb;
            }
        }
        __syncwarp();

        // -- output layer: lane t=lane; lanes 0..3 also t=32+lane --
        float o1[IT] = {}, o2[IT] = {};
        const uint2* owr  = (const uint2*)(sOwH + lane*OWH_STRIDE);
        const uint2* owr2 = (const uint2*)(sOwH + (32+lane)*OWH_STRIDE);
        #pragma unroll 5
        for (int jq = 0; jq < HIDc/4; jq++) {
            uint2 raw = owr[jq];
            float2 w01 = __half22float2(*(__half2*)&raw.x);
            float2 w23 = __half22float2(*(__half2*)&raw.y);
            float4 h0 = *(const float4*)&sH[0*104 + jq*4];
            float4 h1 = *(const float4*)&sH[1*104 + jq*4];
            float4 h2 = *(const float4*)&sH[2*104 + jq*4];
            float4 h3 = *(const float4*)&sH[3*104 + jq*4];
            o1[0] += w01.x*h0.x + w01.y*h0.y + w23.x*h0.z + w23.y*h0.w;
            o1[1] += w01.x*h1.x + w01.y*h1.y + w23.x*h1.z + w23.y*h1.w;
            o1[2] += w01.x*h2.x + w01.y*h2.y + w23.x*h2.z + w23.y*h2.w;
            o1[3] += w01.x*h3.x + w01.y*h3.y + w23.x*h3.z + w23.y*h3.w;
            if (lane < 4) {
                uint2 r2 = owr2[jq];
                float2 v01 = __half22float2(*(__half2*)&r2.x);
                float2 v23 = __half22float2(*(__half2*)&r2.y);
                o2[0] += v01.x*h0.x + v01.y*h0.y + v23.x*h0.z + v23.y*h0.w;
                o2[1] += v01.x*h1.x + v01.y*h1.y + v23.x*h1.z + v23.y*h1.w;
                o2[2] += v01.x*h2.x + v01.y*h2.y + v23.x*h2.z + v23.y*h2.w;
                o2[3] += v01.x*h3.x + v01.y*h3.y + v23.x*h3.z + v23.y*h3.w;
            }
        }
        for (int it = 0; it < nit; it++) {
            out[(long)(base+it)*TAGSc + lane] = o1[it] + sOb[lane];
            if (lane < 4)
                out[(long)(base+it)*TAGSc + 32 + lane] = o2[it] + sOb[32+lane];
        }
        __syncwarp();   // protect sIds/sH before next group's overwrite
    }
}

extern "C" void kernel_launch(void* const* d_in, const int* in_sizes, int n_in,
                              void* d_out, int out_size) {
    const int*   input = (const int*)  d_in[0];
    const float* emb   = (const float*)d_in[1];
    const float* cemb  = (const float*)d_in[2];
    const float* convw = (const float*)d_in[3];
    const float* convb = (const float*)d_in[4];
    const float* fc1w  = (const float*)d_in[5];
    const float* fc1b  = (const float*)d_in[6];
    const float* outw  = (const float*)d_in[7];
    const float* outb  = (const float*)d_in[8];
    float* out = (float*)d_out;

    int nb = in_sizes[0] / ROWI;

    cudaFuncSetAttribute(pos_main, cudaFuncAttributeMaxDynamicSharedMemorySize, SM_BYTES);

    int prep_n = NQ + NWP + NP;
    prep_all<<<(prep_n + 255)/256, 256>>>(convw, cemb, emb, fc1w);

    pos_main<<<148, NT, SM_BYTES>>>(input, emb, convb, fc1w, fc1b, outw, outb, out, nb);
}

// round 4
// speedup vs baseline: 2.5810x; 1.0116x over previous
#include <cuda_runtime.h>
#include <cuda_fp16.h>
#include <math.h>

#define WW    5
#define LL    20
#define ROWI  105      // W*(1+L)
#define CEc   32
#define OCc   30
#define Kc    3
#define WEc   50
#define HIDc  100
#define TAGSc 36
#define QN    256
#define FCIN  400      // (WE+OC)*W
#define WSTR  80       // WE+OC

#define NW 32
#define NT (NW*32)
#define IT 4           // items per warp

#define NQ (WW*QN*HIDc)        // 128000
#define NWP (WW*OCc*HIDc)      // 15000
#define NP (100*OCc)           // 3000

// ---- precomputed tables (device globals: allocation-free scratch) ----
__device__ __half g_P4[100*OCc*4];     // [c][oc][k0,k1,k2,pad]  fp16
__device__ float  g_Q [NQ];            // [w][id][j]
__device__ __half g_WpH[NWP];          // [r=w*30+oc][j]  fp16, pre-transposed

__device__ __forceinline__ float tanh_ap(float x) {
    float y; asm("tanh.approx.f32 %0, %1;" : "=f"(y) : "f"(x)); return y;
}

// one fused prep launch: Q | WpH | P4
__global__ void prep_all(const float* __restrict__ conv_w,
                         const float* __restrict__ char_emb,
                         const float* __restrict__ emb,
                         const float* __restrict__ fc1_w) {
    int i = blockIdx.x*blockDim.x + threadIdx.x;
    if (i < NQ) {
        int j = i % HIDc;
        int c = (i / HIDc) % QN;
        int w = i / (HIDc*QN);
        const float* e  = emb + c*WEc;
        const float* fr = fc1_w + j*FCIN + w*WSTR;
        float s = 0.f;
        #pragma unroll
        for (int d = 0; d < WEc; d++) s += e[d]*fr[d];
        g_Q[i] = s;
    } else if (i < NQ + NWP) {
        int k = i - NQ;
        int j = k % HIDc, r = k / HIDc;
        int w = r / OCc, oc = r % OCc;
        g_WpH[k] = __float2half_rn(fc1_w[j*FCIN + w*WSTR + WEc + oc]);
    } else if (i < NQ + NWP + NP) {
        int k = i - NQ - NWP;
        int oc = k % OCc, c = k / OCc;
        float s0 = 0.f, s1 = 0.f, s2 = 0.f;
        #pragma unroll
        for (int ce = 0; ce < CEc; ce++) {
            float e = char_emb[c*CEc + ce];
            const float* w = &conv_w[(oc*CEc + ce)*Kc];
            s0 += w[0]*e; s1 += w[1]*e; s2 += w[2]*e;
        }
        __half2* dst = (__half2*)&g_P4[k*4];
        dst[0] = __floats2half2_rn(s0, s1);
        dst[1] = __floats2half2_rn(s2, 0.f);
    }
}

// ---- smem layout (bytes) ----
#define OFFB_P4   0          // 24000  half [c][oc][4]
#define OFFB_WPH  24000      // 30000  half [r][100]
#define OFFB_OWH  54000      // 36*216 = 7776  half [t][stride 108]
#define OWH_STRIDE 108       // halves; 216B rows (2-way max bank pattern)
#define OFFB_FB   61776      // 400
#define OFFB_OB   62176      // 160
#define OFFB_CB   62336      // 128
#define OFFB_WS   62464      // warp scratch
#define WSB       4960       // per warp: ids u16 896 | poolT f32 2400 | sH f32 1664
#define SM_BYTES  (OFFB_WS + NW*WSB)   // 221184 = 216KB

__global__ __launch_bounds__(NT) void pos_main(
    const int*   __restrict__ input,
    const float* __restrict__ emb,
    const float* __restrict__ conv_b,
    const float* __restrict__ fc1_w,
    const float* __restrict__ fc1_b,
    const float* __restrict__ out_w,
    const float* __restrict__ out_b,
    float*       __restrict__ out,
    int nb)
{
    extern __shared__ char smb[];
    __half* sP4  = (__half*)(smb + OFFB_P4);
    __half* sWpH = (__half*)(smb + OFFB_WPH);
    __half* sOwH = (__half*)(smb + OFFB_OWH);
    float*  sFb  = (float*)(smb + OFFB_FB);
    float*  sOb  = (float*)(smb + OFFB_OB);
    float*  sCb  = (float*)(smb + OFFB_CB);

    const int tid = threadIdx.x;

    // -- fill shared weights --
    {
        const int4* ps = (const int4*)g_P4;            // 1500 int4
        int4* pd = (int4*)sP4;
        for (int i = tid; i < 1500; i += NT) pd[i] = ps[i];
        const int4* ws = (const int4*)g_WpH;           // 1875 int4
        int4* wd = (int4*)sWpH;
        for (int i = tid; i < 1875; i += NT) wd[i] = ws[i];
        for (int i = tid; i < TAGSc*OWH_STRIDE; i += NT) {
            int t = i / OWH_STRIDE, j = i % OWH_STRIDE;
            sOwH[i] = (j < HIDc) ? __float2half_rn(out_w[t*HIDc + j]) : __half(0.f);
        }
        if (tid < HIDc)  sFb[tid] = fc1_b[tid];
        if (tid < TAGSc) sOb[tid] = out_b[tid];
        if (tid < OCc)   sCb[tid] = conv_b[tid];
    }
    __syncthreads();

    const int warp = tid >> 5, lane = tid & 31;
    char* ws = smb + OFFB_WS + warp*WSB;
    unsigned short* sIds = (unsigned short*)ws;         // 420 used (u16)
    float* sPoolT = (float*)(ws + 896);                 // [r][IT] 600 f
    float* sH     = (float*)(ws + 3296);                // [it][104] 416 f

    const int j0 = lane*4;
    const bool jact = (lane < 25);
    const int ngroups = (nb + IT - 1) / IT;

    for (int group = blockIdx.x*NW + warp; group < ngroups; group += gridDim.x*NW) {
        const int base = group*IT;
        const int nit = (nb - base < IT) ? (nb - base) : IT;

        for (int i = lane; i < nit*ROWI; i += 32)
            sIds[i] = (unsigned short)input[base*ROWI + i];
        __syncwarp();

        // -- fc1 accumulators; word-embedding part via Q table --
        float a[IT][4] = {};
        if (jact) {
            for (int it = 0; it < nit; it++) {
                #pragma unroll
                for (int w = 0; w < WW; w++) {
                    int id = sIds[it*ROWI + w*(1+LL)];
                    if (id < QN) {
                        const float4 q = *(const float4*)&g_Q[(w*QN + id)*HIDc + j0];
                        a[it][0] += q.x; a[it][1] += q.y; a[it][2] += q.z; a[it][3] += q.w;
                    } else {   // exact fallback (never taken for this data)
                        const float* e = emb + (long)id*WEc;
                        #pragma unroll 1
                        for (int d = 0; d < WEc; d++) {
                            float ev = e[d];
                            a[it][0] += ev * fc1_w[(j0+0)*FCIN + w*WSTR + d];
                            a[it][1] += ev * fc1_w[(j0+1)*FCIN + w*WSTR + d];
                            a[it][2] += ev * fc1_w[(j0+2)*FCIN + w*WSTR + d];
                            a[it][3] += ev * fc1_w[(j0+3)*FCIN + w*WSTR + d];
                        }
                    }
                }
            }
        }

        // -- conv + maxpool via fp16 P; lane == oc; rolling 3-window --
        if (lane < OCc) {
            for (int it = 0; it < nit; it++) {
                #pragma unroll 1
                for (int w = 0; w < WW; w++) {
                    const unsigned short* cc = &sIds[it*ROWI + w*(1+LL) + 1];
                    float m = -3.4e38f;
                    float p02 = 0.f, p01 = 0.f, p11 = 0.f;
                    #pragma unroll
                    for (int p = 0; p < LL; p++) {
                        int c = cc[p];
                        uint2 raw = *(const uint2*)&sP4[(c*OCc + lane)*4];
                        float2 f01 = __half22float2(*(__half2*)&raw.x);
                        float  f2  = __low2float(*(__half2*)&raw.y);
                        if (p >= 2) m = fmaxf(m, p02 + p11 + f2);
                        p02 = p01; p01 = f01.x; p11 = f01.y;
                    }
                    sPoolT[(w*OCc + lane)*IT + it] = m + sCb[lane];
                }
            }
        }
        __syncwarp();

        // -- fc1 pooled part: fp16 weights reused across IT items, then tanh --
        if (jact) {
            const uint2* wp = (const uint2*)sWpH;       // row = 25 uint2
            const float4* pp4 = (const float4*)sPoolT;
            #pragma unroll 2
            for (int r = 0; r < WW*OCc; r++) {
                uint2 wraw = wp[r*25 + lane];
                float2 w01 = __half22float2(*(__half2*)&wraw.x);
                float2 w23 = __half22float2(*(__half2*)&wraw.y);
                float4 pv = pp4[r];                     // [item0..3] broadcast
                a[0][0] += pv.x*w01.x; a[0][1] += pv.x*w01.y; a[0][2] += pv.x*w23.x; a[0][3] += pv.x*w23.y;
                a[1][0] += pv.y*w01.x; a[1][1] += pv.y*w01.y; a[1][2] += pv.y*w23.x; a[1][3] += pv.y*w23.y;
                a[2][0] += pv.z*w01.x; a[2][1] += pv.z*w01.y; a[2][2] += pv.z*w23.x; a[2][3] += pv.z*w23.y;
                a[3][0] += pv.w*w01.x; a[3][1] += pv.w*w01.y; a[3][2] += pv.w*w23.x; a[3][3] += pv.w*w23.y;
            }
            #pragma unroll
            for (int it = 0; it < IT; it++) {
                float4 hb;
                hb.x = tanh_ap(a[it][0] + sFb[j0+0]);
                hb.y = tanh_ap(a[it][1] + sFb[j0+1]);
                hb.z = tanh_ap(a[it][2] + sFb[j0+2]);
                hb.w = tanh_ap(a[it][3] + sFb[j0+3]);
                *(float4*)&sH[it*104 + j0] = hb;
            }
        }
        __syncwarp();

        // -- output layer: lane t=lane; lanes 0..3 also t=32+lane --
        float o1[IT] = {}, o2[IT] = {};
        const uint2* owr  = (const uint2*)(sOwH + lane*OWH_STRIDE);
        const uint2* owr2 = (const uint2*)(sOwH + (32+lane)*OWH_STRIDE);
        #pragma unroll 5
        for (int jq = 0; jq < HIDc/4; jq++) {
            uint2 raw = owr[jq];
            float2 w01 = __half22float2(*(__half2*)&raw.x);
            float2 w23 = __half22float2(*(__half2*)&raw.y);
            float4 h0 = *(const float4*)&sH[0*104 + jq*4];
            float4 h1 = *(const float4*)&sH[1*104 + jq*4];
            float4 h2 = *(const float4*)&sH[2*104 + jq*4];
            float4 h3 = *(const float4*)&sH[3*104 + jq*4];
            o1[0] += w01.x*h0.x + w01.y*h0.y + w23.x*h0.z + w23.y*h0.w;
            o1[1] += w01.x*h1.x + w01.y*h1.y + w23.x*h1.z + w23.y*h1.w;
            o1[2] += w01.x*h2.x + w01.y*h2.y + w23.x*h2.z + w23.y*h2.w;
            o1[3] += w01.x*h3.x + w01.y*h3.y + w23.x*h3.z + w23.y*h3.w;
            if (lane < 4) {
                uint2 r2 = owr2[jq];
                float2 v01 = __half22float2(*(__half2*)&r2.x);
                float2 v23 = __half22float2(*(__half2*)&r2.y);
                o2[0] += v01.x*h0.x + v01.y*h0.y + v23.x*h0.z + v23.y*h0.w;
                o2[1] += v01.x*h1.x + v01.y*h1.y + v23.x*h1.z + v23.y*h1.w;
                o2[2] += v01.x*h2.x + v01.y*h2.y + v23.x*h2.z + v23.y*h2.w;
                o2[3] += v01.x*h3.x + v01.y*h3.y + v23.x*h3.z + v23.y*h3.w;
            }
        }
        for (int it = 0; it < nit; it++) {
            out[(long)(base+it)*TAGSc + lane] = o1[it] + sOb[lane];
            if (lane < 4)
                out[(long)(base+it)*TAGSc + 32 + lane] = o2[it] + sOb[32+lane];
        }
        __syncwarp();   // protect sIds/sH before next group's overwrite
    }
}

extern "C" void kernel_launch(void* const* d_in, const int* in_sizes, int n_in,
                              void* d_out, int out_size) {
    const int*   input = (const int*)  d_in[0];
    const float* emb   = (const float*)d_in[1];
    const float* cemb  = (const float*)d_in[2];
    const float* convw = (const float*)d_in[3];
    const float* convb = (const float*)d_in[4];
    const float* fc1w  = (const float*)d_in[5];
    const float* fc1b  = (const float*)d_in[6];
    const float* outw  = (const float*)d_in[7];
    const float* outb  = (const float*)d_in[8];
    float* out = (float*)d_out;

    int nb = in_sizes[0] / ROWI;

    cudaFuncSetAttribute(pos_main, cudaFuncAttributeMaxDynamicSharedMemorySize, SM_BYTES);

    int prep_n = NQ + NWP + NP;
    prep_all<<<(prep_n + 255)/256, 256>>>(convw, cemb, emb, fc1w);

    pos_main<<<148, NT, SM_BYTES>>>(input, emb, convb, fc1w, fc1b, outw, outb, out, nb);
}